// round 1
// baseline (speedup 1.0000x reference)
#include <cuda_runtime.h>
#include <mma.h>
#include <math.h>

using namespace nvcuda;

#define BB   16
#define NN   2048
#define CIN  1475
#define EE   12288
#define DD   (NN*3)          // 6144
#define MM   (BB*NN)         // 32768
#define KSPLIT 8
#define NEG_SLOPE 0.01f

// ---------------- scratch (static device allocations only) ----------------
__device__ float g_buf0[(size_t)MM * 512];   // GEMM output Y
__device__ float g_buf1[(size_t)MM * 512];   // aggregated H
__device__ int   g_cnt[NN];
__device__ int   g_off[NN + 1];
__device__ float g_isd[NN];                  // 1/sqrt(deg)
__device__ float g_invd[NN];                 // 1/deg
__device__ int   g_csr_src[EE];
__device__ float g_csr_norm[EE];
__device__ float g_partial[KSPLIT * BB * DD];
__device__ int   g_is64;

// ---------------- edge dtype detection + accessor ----------------
__device__ __forceinline__ int edge_idx(const void* edges, int i) {
    if (g_is64) return (int)((const long long*)edges)[i];
    return ((const int*)edges)[i];
}

__global__ void k_zero() {
    int i = blockIdx.x * blockDim.x + threadIdx.x;
    if (i < NN) g_cnt[i] = 0;
    if (i == 0) g_is64 = 1;
}

// If data is int64 (little endian, values < 2^31), every odd 32-bit word of
// the first row (src) is 0. Reads stay within the first 2*EE 32-bit words,
// which is safe for either dtype.
__global__ void k_detect(const int* ew) {
    int i = blockIdx.x * blockDim.x + threadIdx.x;
    if (i < EE) {
        if (ew[2 * i + 1] != 0) g_is64 = 0;  // benign race: all writers store 0
    }
}

__global__ void k_count(const void* edges) {
    int e = blockIdx.x * blockDim.x + threadIdx.x;
    if (e < EE) {
        int dst = edge_idx(edges, EE + e);
        atomicAdd(&g_cnt[dst], 1);
    }
}

__global__ void k_scan() {
    if (threadIdx.x == 0) {
        int s = 0;
        for (int n = 0; n < NN; n++) { g_off[n] = s; s += g_cnt[n]; }
        g_off[NN] = s;
    }
    __syncthreads();
    for (int n = threadIdx.x; n < NN; n += blockDim.x) {
        float deg = (float)g_cnt[n] + 1.0f;
        g_isd[n]  = rsqrtf(deg);
        g_invd[n] = 1.0f / deg;
    }
}

// Deterministic CSR fill: thread n scans all edges in order.
__global__ void k_fill(const void* edges) {
    int n = blockIdx.x * blockDim.x + threadIdx.x;
    if (n >= NN) return;
    int pos = g_off[n];
    float isd_n = g_isd[n];
    for (int e = 0; e < EE; e++) {
        int dst = edge_idx(edges, EE + e);
        if (dst == n) {
            int src = edge_idx(edges, e);
            g_csr_src[pos]  = src;
            g_csr_norm[pos] = g_isd[src] * isd_n;
            pos++;
        }
    }
}

// ---------------- tf32 wmma GEMM: C[M,Nc] = A[M,K] @ W[K,Nc] ----------------
#define BM 128
#define BN 128
#define BK 16

__global__ void gemm_tf32(const float* __restrict__ A, const float* __restrict__ W,
                          float* __restrict__ C, int K, int Nc) {
    __shared__ float As[BM][BK];
    __shared__ float Bs[BK][BN];

    const int bm = blockIdx.y * BM;
    const int bn = blockIdx.x * BN;
    const int tid  = threadIdx.x;           // 256 threads
    const int warp = tid >> 5;
    const int wm = warp >> 1;               // 0..3 -> 32 rows each
    const int wn = warp & 1;                // 0..1 -> 64 cols each

    wmma::fragment<wmma::accumulator, 16, 16, 8, float> acc[2][4];
#pragma unroll
    for (int i = 0; i < 2; i++)
#pragma unroll
        for (int j = 0; j < 4; j++)
            wmma::fill_fragment(acc[i][j], 0.0f);

    const int ntiles = (K + BK - 1) / BK;
    for (int t = 0; t < ntiles; t++) {
        const int k0t = t * BK;
        // load A tile 128x16
#pragma unroll
        for (int i = tid; i < BM * BK; i += 256) {
            int r = i >> 4, c = i & 15;
            int gk = k0t + c;
            As[r][c] = (gk < K) ? A[(size_t)(bm + r) * K + gk] : 0.0f;
        }
        // load B tile 16x128
#pragma unroll
        for (int i = tid; i < BK * BN; i += 256) {
            int r = i >> 7, c = i & 127;
            int gk = k0t + r, gn = bn + c;
            Bs[r][c] = (gk < K && gn < Nc) ? W[(size_t)gk * Nc + gn] : 0.0f;
        }
        __syncthreads();

#pragma unroll
        for (int kk = 0; kk < BK; kk += 8) {
            wmma::fragment<wmma::matrix_a, 16, 16, 8, wmma::precision::tf32, wmma::row_major> a[2];
            wmma::fragment<wmma::matrix_b, 16, 16, 8, wmma::precision::tf32, wmma::row_major> b[4];
#pragma unroll
            for (int i = 0; i < 2; i++) {
                wmma::load_matrix_sync(a[i], &As[wm * 32 + i * 16][kk], BK);
#pragma unroll
                for (int q = 0; q < a[i].num_elements; q++)
                    a[i].x[q] = wmma::__float_to_tf32(a[i].x[q]);
            }
#pragma unroll
            for (int j = 0; j < 4; j++) {
                wmma::load_matrix_sync(b[j], &Bs[kk][wn * 64 + j * 16], BN);
#pragma unroll
                for (int q = 0; q < b[j].num_elements; q++)
                    b[j].x[q] = wmma::__float_to_tf32(b[j].x[q]);
            }
#pragma unroll
            for (int i = 0; i < 2; i++)
#pragma unroll
                for (int j = 0; j < 4; j++)
                    wmma::mma_sync(acc[i][j], a[i], b[j], acc[i][j]);
        }
        __syncthreads();
    }

#pragma unroll
    for (int i = 0; i < 2; i++) {
        int gm = bm + wm * 32 + i * 16;
#pragma unroll
        for (int j = 0; j < 4; j++) {
            int gn = bn + wn * 64 + j * 16;
            if (gn + 16 <= Nc)
                wmma::store_matrix_sync(&C[(size_t)gm * Nc + gn], acc[i][j], Nc,
                                        wmma::mem_row_major);
        }
    }
}

// tiny GEMM for layer 5 (K=64, Nc=3), fp32 exact
__global__ void gemm_small(const float* __restrict__ A, const float* __restrict__ W,
                           float* __restrict__ C, int K, int Nc) {
    int m = blockIdx.x * blockDim.x + threadIdx.x;
    if (m >= MM) return;
    for (int n = 0; n < Nc; n++) {
        float acc = 0.0f;
        for (int k = 0; k < K; k++)
            acc += A[(size_t)m * K + k] * W[(size_t)k * Nc + n];
        C[(size_t)m * Nc + n] = acc;
    }
}

// ---------------- GCN aggregation (deterministic gather over CSR) ----------------
__global__ void agg(const float* __restrict__ Y, float* __restrict__ H,
                    const float* __restrict__ bias, int F, int leaky) {
    int bn = blockIdx.x;                 // 0..B*N-1
    int b = bn >> 11;                    // / NN (2048)
    int n = bn & (NN - 1);
    int s = g_off[n], e = g_off[n + 1];
    float idg = g_invd[n];
    const float* Yb = Y + (size_t)b * NN * F;
    for (int f = threadIdx.x; f < F; f += blockDim.x) {
        float acc = Yb[(size_t)n * F + f] * idg + bias[f];
        for (int j = s; j < e; j++)
            acc += Yb[(size_t)g_csr_src[j] * F + f] * g_csr_norm[j];
        if (leaky && acc < 0.0f) acc *= NEG_SLOPE;
        H[(size_t)bn * F + f] = acc;
    }
}

// ---------------- dense head: out = tanh(feat @ Wd + bd) * 0.1 ----------------
// grid: (DD/128, KSPLIT), block 128. Each block: 128 cols, K-chunk of DD/KSPLIT.
__global__ void dense_partial(const float* __restrict__ feat, const float* __restrict__ Wd) {
    __shared__ float sf[BB][128];
    const int n = blockIdx.x * 128 + threadIdx.x;
    const int kbeg = blockIdx.y * (DD / KSPLIT);
    const int kend = kbeg + (DD / KSPLIT);

    float acc[BB];
#pragma unroll
    for (int b = 0; b < BB; b++) acc[b] = 0.0f;

    for (int kc = kbeg; kc < kend; kc += 128) {
        for (int i = threadIdx.x; i < BB * 128; i += 128) {
            int b = i >> 7, k = i & 127;
            sf[b][k] = feat[(size_t)b * DD + kc + k];
        }
        __syncthreads();
#pragma unroll 4
        for (int kk = 0; kk < 128; kk++) {
            float w = Wd[(size_t)(kc + kk) * DD + n];
#pragma unroll
            for (int b = 0; b < BB; b++) acc[b] += sf[b][kk] * w;
        }
        __syncthreads();
    }
#pragma unroll
    for (int b = 0; b < BB; b++)
        g_partial[(size_t)(blockIdx.y * BB + b) * DD + n] = acc[b];
}

__global__ void dense_final(const float* __restrict__ bd, float* __restrict__ out) {
    int n = blockIdx.x * blockDim.x + threadIdx.x;
    if (n >= DD) return;
#pragma unroll
    for (int b = 0; b < BB; b++) {
        float s = bd[n];
#pragma unroll
        for (int j = 0; j < KSPLIT; j++)
            s += g_partial[(size_t)(j * BB + b) * DD + n];
        out[(size_t)b * DD + n] = tanhf(s) * 0.1f;
    }
}

// ---------------- launcher ----------------
extern "C" void kernel_launch(void* const* d_in, const int* in_sizes, int n_in,
                              void* d_out, int out_size) {
    const float* x     = (const float*)d_in[0];
    const void*  edges = d_in[1];
    const float* W[6]  = {(const float*)d_in[2], (const float*)d_in[4],
                          (const float*)d_in[6], (const float*)d_in[8],
                          (const float*)d_in[10], (const float*)d_in[12]};
    const float* bias[6] = {(const float*)d_in[3], (const float*)d_in[5],
                            (const float*)d_in[7], (const float*)d_in[9],
                            (const float*)d_in[11], (const float*)d_in[13]};
    const float* Wd = (const float*)d_in[14];
    const float* bd = (const float*)d_in[15];
    float* out = (float*)d_out;

    float *p0, *p1;
    cudaGetSymbolAddress((void**)&p0, g_buf0);
    cudaGetSymbolAddress((void**)&p1, g_buf1);

    // graph prep
    k_zero<<<(NN + 255) / 256, 256>>>();
    k_detect<<<(EE + 255) / 256, 256>>>((const int*)edges);
    k_count<<<(EE + 255) / 256, 256>>>(edges);
    k_scan<<<1, 1024>>>();
    k_fill<<<2, 1024>>>(edges);

    static const int couts[6] = {512, 512, 256, 256, 64, 3};
    const float* A = x;
    int K = CIN;

    for (int i = 0; i < 5; i++) {
        int Nc = couts[i];
        dim3 grid((Nc + BN - 1) / BN, MM / BM);
        gemm_tf32<<<grid, 256>>>(A, W[i], p0, K, Nc);
        agg<<<MM, 128>>>(p0, p1, bias[i], Nc, (i & 1));
        A = p1;
        K = Nc;
    }
    // layer 5: K=64, Nc=3
    gemm_small<<<MM / 256, 256>>>(p1, W[5], p0, 64, 3);
    agg<<<MM, 128>>>(p0, p1, bias[5], 3, 1);

    // dense head: feat = p1 viewed as [B, DD]
    dense_partial<<<dim3(DD / 128, KSPLIT), 128>>>(p1, Wd);
    dense_final<<<DD / 128, 128>>>(bd, out);
}

// round 2
// speedup vs baseline: 3.0479x; 3.0479x over previous
#include <cuda_runtime.h>
#include <cuda_bf16.h>
#include <mma.h>
#include <math.h>

using namespace nvcuda;

#define BB   16
#define NN   2048
#define CIN  1475
#define KP0  1504            // CIN padded to multiple of 32
#define EE   12288
#define DD   (NN*3)          // 6144
#define MM   (BB*NN)         // 32768
#define KSPLIT 8
#define NEG_SLOPE 0.01f

// ---------------- static device scratch ----------------
__device__ __nv_bfloat16 g_xbf[(size_t)MM * KP0];       // padded bf16 x
__device__ __nv_bfloat16 g_wbf[1504*512 + 512*512 + 512*256 + 256*256 + 256*64];
__device__ __nv_bfloat16 g_hbf0[(size_t)MM * 512];
__device__ __nv_bfloat16 g_hbf1[(size_t)MM * 512];
__device__ float g_yf32[(size_t)MM * 512];              // GEMM fp32 out
__device__ float g_feat[(size_t)MM * 3];
__device__ int   g_cnt[NN];
__device__ int   g_off[NN + 1];
__device__ float g_isd[NN];
__device__ float g_invd[NN];
__device__ int   g_csr_src[EE];
__device__ float g_csr_norm[EE];
__device__ float g_partial[KSPLIT * BB * DD];
__device__ int   g_is64;

// ---------------- edge dtype detection + accessor ----------------
__device__ __forceinline__ int edge_idx(const void* edges, int i) {
    if (g_is64) return (int)((const long long*)edges)[i];
    return ((const int*)edges)[i];
}

__global__ void k_zero() {
    int i = blockIdx.x * blockDim.x + threadIdx.x;
    if (i < NN) g_cnt[i] = 0;
    if (i == 0) g_is64 = 1;
}

__global__ void k_detect(const int* ew) {
    int i = blockIdx.x * blockDim.x + threadIdx.x;
    if (i < EE) {
        if (ew[2 * i + 1] != 0) g_is64 = 0;
    }
}

__global__ void k_count(const void* edges) {
    int e = blockIdx.x * blockDim.x + threadIdx.x;
    if (e < EE) atomicAdd(&g_cnt[edge_idx(edges, EE + e)], 1);
}

// parallel inclusive scan over 2048 counts (1 block, 1024 threads)
__global__ void k_scan() {
    __shared__ int sA[NN], sB[NN];
    int tid = threadIdx.x;
    for (int i = tid; i < NN; i += 1024) sA[i] = g_cnt[i];
    __syncthreads();
    int* cur = sA; int* nxt = sB;
    for (int off = 1; off < NN; off <<= 1) {
        for (int i = tid; i < NN; i += 1024)
            nxt[i] = cur[i] + (i >= off ? cur[i - off] : 0);
        __syncthreads();
        int* t = cur; cur = nxt; nxt = t;
    }
    for (int i = tid; i < NN; i += 1024) {
        g_off[i] = cur[i] - g_cnt[i];           // exclusive
        float deg = (float)g_cnt[i] + 1.0f;
        g_isd[i]  = rsqrtf(deg);
        g_invd[i] = 1.0f / deg;
    }
    if (tid == 0) g_off[NN] = cur[NN - 1];
}

// deterministic CSR fill; dst list cached in shared (48KB)
__global__ void k_fill(const void* edges) {
    __shared__ int sdst[EE];
    for (int e = threadIdx.x; e < EE; e += 1024) sdst[e] = edge_idx(edges, EE + e);
    __syncthreads();
    int n = blockIdx.x * 1024 + threadIdx.x;
    int pos = g_off[n];
    float isd_n = g_isd[n];
    for (int e = 0; e < EE; e++) {
        if (sdst[e] == n) {
            int src = edge_idx(edges, e);
            g_csr_src[pos]  = src;
            g_csr_norm[pos] = g_isd[src] * isd_n;
            pos++;
        }
    }
}

// ---------------- conversions ----------------
__global__ void x2bf(const float* __restrict__ src, __nv_bfloat16* __restrict__ dst) {
    size_t i = (size_t)blockIdx.x * blockDim.x + threadIdx.x;
    size_t total = (size_t)MM * KP0;
    if (i >= total) return;
    int r = (int)(i / KP0), c = (int)(i % KP0);
    dst[i] = (c < CIN) ? __float2bfloat16(src[(size_t)r * CIN + c]) : __float2bfloat16(0.0f);
}

__global__ void w2bf(const float* __restrict__ W, __nv_bfloat16* __restrict__ dst,
                     int K, int Kp, int Nc) {
    int i = blockIdx.x * blockDim.x + threadIdx.x;
    if (i >= Kp * Nc) return;
    int r = i / Nc, c = i % Nc;
    dst[i] = (r < K) ? __float2bfloat16(W[(size_t)r * Nc + c]) : __float2bfloat16(0.0f);
}

// ---------------- cp.async helpers ----------------
__device__ __forceinline__ void cp_async16(void* smem, const void* gmem, int src_bytes) {
    unsigned sa = (unsigned)__cvta_generic_to_shared(smem);
    asm volatile("cp.async.cg.shared.global [%0], [%1], 16, %2;\n"
                 :: "r"(sa), "l"(gmem), "r"(src_bytes));
}
__device__ __forceinline__ void cp_commit() { asm volatile("cp.async.commit_group;\n"); }
template<int N> __device__ __forceinline__ void cp_wait() {
    asm volatile("cp.async.wait_group %0;\n" :: "n"(N));
}

// ---------------- bf16 wmma GEMM: C[M,Nc] = A[M,Kp] @ W[Kp,Nc] ----------------
// 128x128x32 tiles, double-buffered cp.async, 256 threads (8 warps, 4x2)
#define ASTR 48
#define BSTR 144

__global__ __launch_bounds__(256) void gemm_bf16(
        const __nv_bfloat16* __restrict__ A, const __nv_bfloat16* __restrict__ Wt,
        float* __restrict__ C, int lda, int Kp, int Nc) {
    __shared__ __nv_bfloat16 As[2][128][ASTR];
    __shared__ __nv_bfloat16 Bs[2][32][BSTR];

    const int tid = threadIdx.x;
    const int bm = blockIdx.y * 128;
    const int bn = blockIdx.x * 128;
    const int warp = tid >> 5;
    const int wm = warp >> 1;
    const int wn = warp & 1;

    wmma::fragment<wmma::accumulator, 16, 16, 16, float> acc[2][4];
#pragma unroll
    for (int i = 0; i < 2; i++)
#pragma unroll
        for (int j = 0; j < 4; j++) wmma::fill_fragment(acc[i][j], 0.0f);

    const int T = Kp / 32;

    auto loadTiles = [&](int t, int s) {
        const int k0 = t * 32;
#pragma unroll
        for (int v = tid; v < 512; v += 256) {         // A: 128x32, 8-elem vecs
            int r = v >> 2, c = (v & 3) * 8;
            cp_async16(&As[s][r][c], A + (size_t)(bm + r) * lda + k0 + c, 16);
        }
#pragma unroll
        for (int v = tid; v < 512; v += 256) {         // B: 32x128
            int r = v >> 4, c = (v & 15) * 8;
            int gn = bn + c;
            cp_async16(&Bs[s][r][c], Wt + (size_t)(k0 + r) * Nc + gn, (gn < Nc) ? 16 : 0);
        }
        cp_commit();
    };

    loadTiles(0, 0);
    for (int t = 0; t < T; t++) {
        const int cur = t & 1;
        if (t + 1 < T) { loadTiles(t + 1, cur ^ 1); cp_wait<1>(); }
        else           { cp_wait<0>(); }
        __syncthreads();

#pragma unroll
        for (int kk = 0; kk < 32; kk += 16) {
            wmma::fragment<wmma::matrix_a, 16, 16, 16, __nv_bfloat16, wmma::row_major> a[2];
            wmma::fragment<wmma::matrix_b, 16, 16, 16, __nv_bfloat16, wmma::row_major> b[4];
#pragma unroll
            for (int i = 0; i < 2; i++)
                wmma::load_matrix_sync(a[i], &As[cur][wm * 32 + i * 16][kk], ASTR);
#pragma unroll
            for (int j = 0; j < 4; j++)
                wmma::load_matrix_sync(b[j], &Bs[cur][kk][wn * 64 + j * 16], BSTR);
#pragma unroll
            for (int i = 0; i < 2; i++)
#pragma unroll
                for (int j = 0; j < 4; j++)
                    wmma::mma_sync(acc[i][j], a[i], b[j], acc[i][j]);
        }
        __syncthreads();
    }

#pragma unroll
    for (int i = 0; i < 2; i++) {
        int gm = bm + wm * 32 + i * 16;
#pragma unroll
        for (int j = 0; j < 4; j++) {
            int gn = bn + wn * 64 + j * 16;
            if (gn + 16 <= Nc)
                wmma::store_matrix_sync(&C[(size_t)gm * Nc + gn], acc[i][j], Nc,
                                        wmma::mem_row_major);
        }
    }
}

// layer 5: A bf16 [M,64] @ W fp32 [64,3]
__global__ void gemm_small_bf(const __nv_bfloat16* __restrict__ A,
                              const float* __restrict__ W, float* __restrict__ C) {
    int m = blockIdx.x * blockDim.x + threadIdx.x;
    if (m >= MM) return;
    float a0 = 0, a1 = 0, a2 = 0;
#pragma unroll
    for (int k = 0; k < 64; k++) {
        float a = __bfloat162float(A[(size_t)m * 64 + k]);
        a0 += a * W[k * 3 + 0];
        a1 += a * W[k * 3 + 1];
        a2 += a * W[k * 3 + 2];
    }
    C[(size_t)m * 3 + 0] = a0;
    C[(size_t)m * 3 + 1] = a1;
    C[(size_t)m * 3 + 2] = a2;
}

// ---------------- aggregation (float4 gather, writes bf16) ----------------
// blockDim = npb * (F/4). npb nodes per block.
__global__ void agg_vec4(const float* __restrict__ Y, __nv_bfloat16* __restrict__ Hbf,
                         const float* __restrict__ bias, int F, int leaky, int npb) {
    const int lanes = F >> 2;
    const int local = threadIdx.x / lanes;
    const int f4 = threadIdx.x % lanes;
    const int bn = blockIdx.x * npb + local;
    const int b = bn >> 11;
    const int n = bn & (NN - 1);
    const int s = g_off[n], e = g_off[n + 1];
    const float idg = g_invd[n];
    const float4* Yb = (const float4*)(Y + (size_t)b * NN * F);
    const int ld4 = F >> 2;

    float4 v = Yb[(size_t)n * ld4 + f4];
    float4 bi = ((const float4*)bias)[f4];
    float4 acc = make_float4(v.x * idg + bi.x, v.y * idg + bi.y,
                             v.z * idg + bi.z, v.w * idg + bi.w);
    for (int j = s; j < e; j++) {
        int src = g_csr_src[j];
        float nm = g_csr_norm[j];
        float4 y = Yb[(size_t)src * ld4 + f4];
        acc.x += y.x * nm; acc.y += y.y * nm; acc.z += y.z * nm; acc.w += y.w * nm;
    }
    if (leaky) {
        if (acc.x < 0.f) acc.x *= NEG_SLOPE;
        if (acc.y < 0.f) acc.y *= NEG_SLOPE;
        if (acc.z < 0.f) acc.z *= NEG_SLOPE;
        if (acc.w < 0.f) acc.w *= NEG_SLOPE;
    }
    __nv_bfloat162 lo = __floats2bfloat162_rn(acc.x, acc.y);
    __nv_bfloat162 hi = __floats2bfloat162_rn(acc.z, acc.w);
    uint2 pack = make_uint2(*(unsigned*)&lo, *(unsigned*)&hi);
    ((uint2*)(Hbf + (size_t)bn * F))[f4] = pack;
}

// last layer F=3: writes fp32 feat, with leaky
__global__ void agg_last(const float* __restrict__ Y, float* __restrict__ Hf) {
    int idx = blockIdx.x * blockDim.x + threadIdx.x;
    if (idx >= MM * 3) return;
    int bn = idx / 3, f = idx % 3;
    int b = bn >> 11, n = bn & (NN - 1);
    int s = g_off[n], e = g_off[n + 1];
    const float* Yb = Y + (size_t)b * NN * 3;
    float acc = Yb[(size_t)n * 3 + f] * g_invd[n];
    for (int j = s; j < e; j++)
        acc += Yb[(size_t)g_csr_src[j] * 3 + f] * g_csr_norm[j];
    if (acc < 0.f) acc *= NEG_SLOPE;
    Hf[idx] = acc;
}

// bias for last layer folded into agg_last? No — bias applied pre-activation.
// Keep it in gemm_small output instead (cheap): separate tiny kernel.
__global__ void add_bias3(float* __restrict__ C, const float* __restrict__ b5) {
    // NOTE: bias must be added AFTER aggregation (reference: agg + h*invd + b).
    // Handled in agg_last2 below instead. (unused)
}

// ---------------- dense head ----------------
__global__ void dense_partial(const float* __restrict__ feat, const float* __restrict__ Wd) {
    __shared__ float sf[BB][128];
    const int n = blockIdx.x * 128 + threadIdx.x;
    const int kbeg = blockIdx.y * (DD / KSPLIT);
    const int kend = kbeg + (DD / KSPLIT);

    float acc[BB];
#pragma unroll
    for (int b = 0; b < BB; b++) acc[b] = 0.0f;

    for (int kc = kbeg; kc < kend; kc += 128) {
        for (int i = threadIdx.x; i < BB * 128; i += 128) {
            int b = i >> 7, k = i & 127;
            sf[b][k] = feat[(size_t)b * DD + kc + k];
        }
        __syncthreads();
#pragma unroll 4
        for (int kk = 0; kk < 128; kk++) {
            float w = Wd[(size_t)(kc + kk) * DD + n];
#pragma unroll
            for (int b = 0; b < BB; b++) acc[b] += sf[b][kk] * w;
        }
        __syncthreads();
    }
#pragma unroll
    for (int b = 0; b < BB; b++)
        g_partial[(size_t)(blockIdx.y * BB + b) * DD + n] = acc[b];
}

__global__ void dense_final(const float* __restrict__ bd, float* __restrict__ out) {
    int n = blockIdx.x * blockDim.x + threadIdx.x;
    if (n >= DD) return;
#pragma unroll
    for (int b = 0; b < BB; b++) {
        float s = bd[n];
#pragma unroll
        for (int j = 0; j < KSPLIT; j++)
            s += g_partial[(size_t)(j * BB + b) * DD + n];
        out[(size_t)b * DD + n] = tanhf(s) * 0.1f;
    }
}

// last-layer agg with bias (F=3)
__global__ void agg_last2(const float* __restrict__ Y, float* __restrict__ Hf,
                          const float* __restrict__ b5) {
    int idx = blockIdx.x * blockDim.x + threadIdx.x;
    if (idx >= MM * 3) return;
    int bn = idx / 3, f = idx % 3;
    int b = bn >> 11, n = bn & (NN - 1);
    int s = g_off[n], e = g_off[n + 1];
    const float* Yb = Y + (size_t)b * NN * 3;
    float acc = Yb[(size_t)n * 3 + f] * g_invd[n] + b5[f];
    for (int j = s; j < e; j++)
        acc += Yb[(size_t)g_csr_src[j] * 3 + f] * g_csr_norm[j];
    if (acc < 0.f) acc *= NEG_SLOPE;
    Hf[idx] = acc;
}

// ---------------- launcher ----------------
extern "C" void kernel_launch(void* const* d_in, const int* in_sizes, int n_in,
                              void* d_out, int out_size) {
    const float* x     = (const float*)d_in[0];
    const void*  edges = d_in[1];
    const float* W[6]  = {(const float*)d_in[2], (const float*)d_in[4],
                          (const float*)d_in[6], (const float*)d_in[8],
                          (const float*)d_in[10], (const float*)d_in[12]};
    const float* bias[6] = {(const float*)d_in[3], (const float*)d_in[5],
                            (const float*)d_in[7], (const float*)d_in[9],
                            (const float*)d_in[11], (const float*)d_in[13]};
    const float* Wd = (const float*)d_in[14];
    const float* bd = (const float*)d_in[15];
    float* out = (float*)d_out;

    __nv_bfloat16 *xbf, *wbf, *hb0, *hb1;
    float *yf, *feat;
    cudaGetSymbolAddress((void**)&xbf, g_xbf);
    cudaGetSymbolAddress((void**)&wbf, g_wbf);
    cudaGetSymbolAddress((void**)&hb0, g_hbf0);
    cudaGetSymbolAddress((void**)&hb1, g_hbf1);
    cudaGetSymbolAddress((void**)&yf, g_yf32);
    cudaGetSymbolAddress((void**)&feat, g_feat);

    // graph prep
    k_zero<<<(NN + 255) / 256, 256>>>();
    k_detect<<<(EE + 255) / 256, 256>>>((const int*)edges);
    k_count<<<(EE + 255) / 256, 256>>>(edges);
    k_scan<<<1, 1024>>>();
    k_fill<<<2, 1024>>>(edges);

    // conversions
    {
        size_t total = (size_t)MM * KP0;
        x2bf<<<(unsigned)((total + 255) / 256), 256>>>(x, xbf);
    }
    static const int Ks[5]  = {CIN, 512, 512, 256, 256};
    static const int Kps[5] = {KP0, 512, 512, 256, 256};
    static const int Ncs[5] = {512, 512, 256, 256, 64};
    size_t woff[5];
    {
        size_t o = 0;
        for (int i = 0; i < 5; i++) {
            woff[i] = o;
            o += (size_t)Kps[i] * Ncs[i];
            int tot = Kps[i] * Ncs[i];
            w2bf<<<(tot + 255) / 256, 256>>>(W[i], wbf + woff[i], Ks[i], Kps[i], Ncs[i]);
        }
    }

    // 5 tensor-core layers
    const __nv_bfloat16* A = xbf;
    for (int i = 0; i < 5; i++) {
        int Nc = Ncs[i], Kp = Kps[i];
        int lda = (i == 0) ? KP0 : Ncs[i - 1];
        dim3 grid((Nc + 127) / 128, MM / 128);
        gemm_bf16<<<grid, 256>>>(A, wbf + woff[i], yf, lda, Kp, Nc);
        __nv_bfloat16* Hout = (i & 1) ? hb1 : hb0;
        int npb = 128 / (Nc >> 2) > 0 ? (128 / (Nc >> 2)) : 1;  // 512->1, 256->2, 64->8
        if (npb < 1) npb = 1;
        int bd_threads = npb * (Nc >> 2);
        agg_vec4<<<MM / npb, bd_threads>>>(yf, Hout, bias[i], Nc, (i & 1), npb);
        A = Hout;
    }

    // layer 5: K=64, Nc=3, then agg with bias + leaky -> feat fp32
    gemm_small_bf<<<MM / 256, 256>>>(A, W[5], yf);
    agg_last2<<<(MM * 3 + 255) / 256, 256>>>(yf, feat, bias[5]);

    // dense head
    dense_partial<<<dim3(DD / 128, KSPLIT), 128>>>(feat, Wd);
    dense_final<<<DD / 128, 128>>>(bd, out);
}

// round 3
// speedup vs baseline: 3.0654x; 1.0057x over previous
#include <cuda_runtime.h>
#include <cuda_bf16.h>
#include <mma.h>
#include <math.h>

using namespace nvcuda;

#define BB   16
#define NN   2048
#define CIN  1475
#define KP0  1504            // CIN padded to multiple of 32
#define EE   12288
#define DD   (NN*3)          // 6144
#define MM   (BB*NN)         // 32768
#define KSPLIT 8
#define NEG_SLOPE 0.01f

// ---------------- static device scratch ----------------
__device__ __nv_bfloat16 g_xbf[(size_t)MM * KP0];       // padded bf16 x
__device__ __nv_bfloat16 g_wbf[1504*512 + 512*512 + 512*256 + 256*256 + 256*64];
__device__ __nv_bfloat16 g_hbf0[(size_t)MM * 512];
__device__ __nv_bfloat16 g_hbf1[(size_t)MM * 512];
__device__ float g_yf32[(size_t)MM * 512];              // GEMM fp32 out
__device__ float g_feat[(size_t)MM * 3];
__device__ int   g_cnt[NN];
__device__ int   g_off[NN + 1];
__device__ float g_isd[NN];
__device__ float g_invd[NN];
__device__ int   g_csr_src[EE];
__device__ float g_csr_norm[EE];
__device__ float g_partial[KSPLIT * BB * DD];
__device__ int   g_is64;

// ---------------- edge dtype detection + accessor ----------------
__device__ __forceinline__ int edge_idx(const void* edges, int i) {
    if (g_is64) return (int)((const long long*)edges)[i];
    return ((const int*)edges)[i];
}

__global__ void k_zero() {
    int i = blockIdx.x * blockDim.x + threadIdx.x;
    if (i < NN) g_cnt[i] = 0;
    if (i == 0) g_is64 = 1;
}

__global__ void k_detect(const int* ew) {
    int i = blockIdx.x * blockDim.x + threadIdx.x;
    if (i < EE) {
        if (ew[2 * i + 1] != 0) g_is64 = 0;
    }
}

__global__ void k_count(const void* edges) {
    int e = blockIdx.x * blockDim.x + threadIdx.x;
    if (e < EE) atomicAdd(&g_cnt[edge_idx(edges, EE + e)], 1);
}

// parallel inclusive scan over 2048 counts (1 block, 1024 threads)
__global__ void k_scan() {
    __shared__ int sA[NN], sB[NN];
    int tid = threadIdx.x;
    for (int i = tid; i < NN; i += 1024) sA[i] = g_cnt[i];
    __syncthreads();
    int* cur = sA; int* nxt = sB;
    for (int off = 1; off < NN; off <<= 1) {
        for (int i = tid; i < NN; i += 1024)
            nxt[i] = cur[i] + (i >= off ? cur[i - off] : 0);
        __syncthreads();
        int* t = cur; cur = nxt; nxt = t;
    }
    for (int i = tid; i < NN; i += 1024) {
        g_off[i] = cur[i] - g_cnt[i];           // exclusive
        float deg = (float)g_cnt[i] + 1.0f;
        g_isd[i]  = rsqrtf(deg);
        g_invd[i] = 1.0f / deg;
    }
    if (tid == 0) g_off[NN] = cur[NN - 1];
}

// deterministic CSR fill; dst list cached in shared (48KB)
__global__ void k_fill(const void* edges) {
    __shared__ int sdst[EE];
    for (int e = threadIdx.x; e < EE; e += 1024) sdst[e] = edge_idx(edges, EE + e);
    __syncthreads();
    int n = blockIdx.x * 1024 + threadIdx.x;
    int pos = g_off[n];
    float isd_n = g_isd[n];
    for (int e = 0; e < EE; e++) {
        if (sdst[e] == n) {
            int src = edge_idx(edges, e);
            g_csr_src[pos]  = src;
            g_csr_norm[pos] = g_isd[src] * isd_n;
            pos++;
        }
    }
}

// ---------------- conversions ----------------
__global__ void x2bf(const float* __restrict__ src, __nv_bfloat16* __restrict__ dst) {
    size_t i = (size_t)blockIdx.x * blockDim.x + threadIdx.x;
    size_t total = (size_t)MM * KP0;
    if (i >= total) return;
    int r = (int)(i / KP0), c = (int)(i % KP0);
    dst[i] = (c < CIN) ? __float2bfloat16(src[(size_t)r * CIN + c]) : __float2bfloat16(0.0f);
}

__global__ void w2bf(const float* __restrict__ W, __nv_bfloat16* __restrict__ dst,
                     int K, int Kp, int Nc) {
    int i = blockIdx.x * blockDim.x + threadIdx.x;
    if (i >= Kp * Nc) return;
    int r = i / Nc, c = i % Nc;
    dst[i] = (r < K) ? __float2bfloat16(W[(size_t)r * Nc + c]) : __float2bfloat16(0.0f);
}

// ---------------- cp.async helpers ----------------
__device__ __forceinline__ void cp_async16(void* smem, const void* gmem, int src_bytes) {
    unsigned sa = (unsigned)__cvta_generic_to_shared(smem);
    asm volatile("cp.async.cg.shared.global [%0], [%1], 16, %2;\n"
                 :: "r"(sa), "l"(gmem), "r"(src_bytes));
}
__device__ __forceinline__ void cp_commit() { asm volatile("cp.async.commit_group;\n"); }
template<int N> __device__ __forceinline__ void cp_wait() {
    asm volatile("cp.async.wait_group %0;\n" :: "n"(N));
}

// ---------------- bf16 wmma GEMM: C[M,Nc] = A[M,Kp] @ W[Kp,Nc] ----------------
// 128x128x32 tiles, double-buffered cp.async, 256 threads (8 warps, 4x2)
#define ASTR 48
#define BSTR 144

__global__ __launch_bounds__(256) void gemm_bf16(
        const __nv_bfloat16* __restrict__ A, const __nv_bfloat16* __restrict__ Wt,
        float* __restrict__ C, int lda, int Kp, int Nc) {
    __shared__ __nv_bfloat16 As[2][128][ASTR];
    __shared__ __nv_bfloat16 Bs[2][32][BSTR];

    const int tid = threadIdx.x;
    const int bm = blockIdx.y * 128;
    const int bn = blockIdx.x * 128;
    const int warp = tid >> 5;
    const int wm = warp >> 1;
    const int wn = warp & 1;

    wmma::fragment<wmma::accumulator, 16, 16, 16, float> acc[2][4];
#pragma unroll
    for (int i = 0; i < 2; i++)
#pragma unroll
        for (int j = 0; j < 4; j++) wmma::fill_fragment(acc[i][j], 0.0f);

    const int T = Kp / 32;

    auto loadTiles = [&](int t, int s) {
        const int k0 = t * 32;
#pragma unroll
        for (int v = tid; v < 512; v += 256) {         // A: 128x32, 8-elem vecs
            int r = v >> 2, c = (v & 3) * 8;
            cp_async16(&As[s][r][c], A + (size_t)(bm + r) * lda + k0 + c, 16);
        }
#pragma unroll
        for (int v = tid; v < 512; v += 256) {         // B: 32x128
            int r = v >> 4, c = (v & 15) * 8;
            int gn = bn + c;
            cp_async16(&Bs[s][r][c], Wt + (size_t)(k0 + r) * Nc + gn, (gn < Nc) ? 16 : 0);
        }
        cp_commit();
    };

    loadTiles(0, 0);
    for (int t = 0; t < T; t++) {
        const int cur = t & 1;
        if (t + 1 < T) { loadTiles(t + 1, cur ^ 1); cp_wait<1>(); }
        else           { cp_wait<0>(); }
        __syncthreads();

#pragma unroll
        for (int kk = 0; kk < 32; kk += 16) {
            wmma::fragment<wmma::matrix_a, 16, 16, 16, __nv_bfloat16, wmma::row_major> a[2];
            wmma::fragment<wmma::matrix_b, 16, 16, 16, __nv_bfloat16, wmma::row_major> b[4];
#pragma unroll
            for (int i = 0; i < 2; i++)
                wmma::load_matrix_sync(a[i], &As[cur][wm * 32 + i * 16][kk], ASTR);
#pragma unroll
            for (int j = 0; j < 4; j++)
                wmma::load_matrix_sync(b[j], &Bs[cur][kk][wn * 64 + j * 16], BSTR);
#pragma unroll
            for (int i = 0; i < 2; i++)
#pragma unroll
                for (int j = 0; j < 4; j++)
                    wmma::mma_sync(acc[i][j], a[i], b[j], acc[i][j]);
        }
        __syncthreads();
    }

#pragma unroll
    for (int i = 0; i < 2; i++) {
        int gm = bm + wm * 32 + i * 16;
#pragma unroll
        for (int j = 0; j < 4; j++) {
            int gn = bn + wn * 64 + j * 16;
            if (gn + 16 <= Nc)
                wmma::store_matrix_sync(&C[(size_t)gm * Nc + gn], acc[i][j], Nc,
                                        wmma::mem_row_major);
        }
    }
}

// layer 5: A bf16 [M,64] @ W fp32 [64,3]
__global__ void gemm_small_bf(const __nv_bfloat16* __restrict__ A,
                              const float* __restrict__ W, float* __restrict__ C) {
    int m = blockIdx.x * blockDim.x + threadIdx.x;
    if (m >= MM) return;
    float a0 = 0, a1 = 0, a2 = 0;
#pragma unroll
    for (int k = 0; k < 64; k++) {
        float a = __bfloat162float(A[(size_t)m * 64 + k]);
        a0 += a * W[k * 3 + 0];
        a1 += a * W[k * 3 + 1];
        a2 += a * W[k * 3 + 2];
    }
    C[(size_t)m * 3 + 0] = a0;
    C[(size_t)m * 3 + 1] = a1;
    C[(size_t)m * 3 + 2] = a2;
}

// ---------------- aggregation (float4 gather, writes bf16) ----------------
// blockDim = npb * (F/4). npb nodes per block.
__global__ void agg_vec4(const float* __restrict__ Y, __nv_bfloat16* __restrict__ Hbf,
                         const float* __restrict__ bias, int F, int leaky, int npb) {
    const int lanes = F >> 2;
    const int local = threadIdx.x / lanes;
    const int f4 = threadIdx.x % lanes;
    const int bn = blockIdx.x * npb + local;
    const int b = bn >> 11;
    const int n = bn & (NN - 1);
    const int s = g_off[n], e = g_off[n + 1];
    const float idg = g_invd[n];
    const float4* Yb = (const float4*)(Y + (size_t)b * NN * F);
    const int ld4 = F >> 2;

    float4 v = Yb[(size_t)n * ld4 + f4];
    float4 bi = ((const float4*)bias)[f4];
    float4 acc = make_float4(v.x * idg + bi.x, v.y * idg + bi.y,
                             v.z * idg + bi.z, v.w * idg + bi.w);
    for (int j = s; j < e; j++) {
        int src = g_csr_src[j];
        float nm = g_csr_norm[j];
        float4 y = Yb[(size_t)src * ld4 + f4];
        acc.x += y.x * nm; acc.y += y.y * nm; acc.z += y.z * nm; acc.w += y.w * nm;
    }
    if (leaky) {
        if (acc.x < 0.f) acc.x *= NEG_SLOPE;
        if (acc.y < 0.f) acc.y *= NEG_SLOPE;
        if (acc.z < 0.f) acc.z *= NEG_SLOPE;
        if (acc.w < 0.f) acc.w *= NEG_SLOPE;
    }
    __nv_bfloat162 lo = __floats2bfloat162_rn(acc.x, acc.y);
    __nv_bfloat162 hi = __floats2bfloat162_rn(acc.z, acc.w);
    uint2 pack = make_uint2(*(unsigned*)&lo, *(unsigned*)&hi);
    ((uint2*)(Hbf + (size_t)bn * F))[f4] = pack;
}

// last layer F=3: writes fp32 feat, with leaky
__global__ void agg_last(const float* __restrict__ Y, float* __restrict__ Hf) {
    int idx = blockIdx.x * blockDim.x + threadIdx.x;
    if (idx >= MM * 3) return;
    int bn = idx / 3, f = idx % 3;
    int b = bn >> 11, n = bn & (NN - 1);
    int s = g_off[n], e = g_off[n + 1];
    const float* Yb = Y + (size_t)b * NN * 3;
    float acc = Yb[(size_t)n * 3 + f] * g_invd[n];
    for (int j = s; j < e; j++)
        acc += Yb[(size_t)g_csr_src[j] * 3 + f] * g_csr_norm[j];
    if (acc < 0.f) acc *= NEG_SLOPE;
    Hf[idx] = acc;
}

// bias for last layer folded into agg_last? No — bias applied pre-activation.
// Keep it in gemm_small output instead (cheap): separate tiny kernel.
__global__ void add_bias3(float* __restrict__ C, const float* __restrict__ b5) {
    // NOTE: bias must be added AFTER aggregation (reference: agg + h*invd + b).
    // Handled in agg_last2 below instead. (unused)
}

// ---------------- dense head ----------------
__global__ void dense_partial(const float* __restrict__ feat, const float* __restrict__ Wd) {
    __shared__ float sf[BB][128];
    const int n = blockIdx.x * 128 + threadIdx.x;
    const int kbeg = blockIdx.y * (DD / KSPLIT);
    const int kend = kbeg + (DD / KSPLIT);

    float acc[BB];
#pragma unroll
    for (int b = 0; b < BB; b++) acc[b] = 0.0f;

    for (int kc = kbeg; kc < kend; kc += 128) {
        for (int i = threadIdx.x; i < BB * 128; i += 128) {
            int b = i >> 7, k = i & 127;
            sf[b][k] = feat[(size_t)b * DD + kc + k];
        }
        __syncthreads();
#pragma unroll 4
        for (int kk = 0; kk < 128; kk++) {
            float w = Wd[(size_t)(kc + kk) * DD + n];
#pragma unroll
            for (int b = 0; b < BB; b++) acc[b] += sf[b][kk] * w;
        }
        __syncthreads();
    }
#pragma unroll
    for (int b = 0; b < BB; b++)
        g_partial[(size_t)(blockIdx.y * BB + b) * DD + n] = acc[b];
}

__global__ void dense_final(const float* __restrict__ bd, float* __restrict__ out) {
    int n = blockIdx.x * blockDim.x + threadIdx.x;
    if (n >= DD) return;
#pragma unroll
    for (int b = 0; b < BB; b++) {
        float s = bd[n];
#pragma unroll
        for (int j = 0; j < KSPLIT; j++)
            s += g_partial[(size_t)(j * BB + b) * DD + n];
        out[(size_t)b * DD + n] = tanhf(s) * 0.1f;
    }
}

// last-layer agg with bias (F=3)
__global__ void agg_last2(const float* __restrict__ Y, float* __restrict__ Hf,
                          const float* __restrict__ b5) {
    int idx = blockIdx.x * blockDim.x + threadIdx.x;
    if (idx >= MM * 3) return;
    int bn = idx / 3, f = idx % 3;
    int b = bn >> 11, n = bn & (NN - 1);
    int s = g_off[n], e = g_off[n + 1];
    const float* Yb = Y + (size_t)b * NN * 3;
    float acc = Yb[(size_t)n * 3 + f] * g_invd[n] + b5[f];
    for (int j = s; j < e; j++)
        acc += Yb[(size_t)g_csr_src[j] * 3 + f] * g_csr_norm[j];
    if (acc < 0.f) acc *= NEG_SLOPE;
    Hf[idx] = acc;
}

// ---------------- launcher ----------------
extern "C" void kernel_launch(void* const* d_in, const int* in_sizes, int n_in,
                              void* d_out, int out_size) {
    const float* x     = (const float*)d_in[0];
    const void*  edges = d_in[1];
    const float* W[6]  = {(const float*)d_in[2], (const float*)d_in[4],
                          (const float*)d_in[6], (const float*)d_in[8],
                          (const float*)d_in[10], (const float*)d_in[12]};
    const float* bias[6] = {(const float*)d_in[3], (const float*)d_in[5],
                            (const float*)d_in[7], (const float*)d_in[9],
                            (const float*)d_in[11], (const float*)d_in[13]};
    const float* Wd = (const float*)d_in[14];
    const float* bd = (const float*)d_in[15];
    float* out = (float*)d_out;

    __nv_bfloat16 *xbf, *wbf, *hb0, *hb1;
    float *yf, *feat;
    cudaGetSymbolAddress((void**)&xbf, g_xbf);
    cudaGetSymbolAddress((void**)&wbf, g_wbf);
    cudaGetSymbolAddress((void**)&hb0, g_hbf0);
    cudaGetSymbolAddress((void**)&hb1, g_hbf1);
    cudaGetSymbolAddress((void**)&yf, g_yf32);
    cudaGetSymbolAddress((void**)&feat, g_feat);

    // graph prep
    k_zero<<<(NN + 255) / 256, 256>>>();
    k_detect<<<(EE + 255) / 256, 256>>>((const int*)edges);
    k_count<<<(EE + 255) / 256, 256>>>(edges);
    k_scan<<<1, 1024>>>();
    k_fill<<<2, 1024>>>(edges);

    // conversions
    {
        size_t total = (size_t)MM * KP0;
        x2bf<<<(unsigned)((total + 255) / 256), 256>>>(x, xbf);
    }
    static const int Ks[5]  = {CIN, 512, 512, 256, 256};
    static const int Kps[5] = {KP0, 512, 512, 256, 256};
    static const int Ncs[5] = {512, 512, 256, 256, 64};
    size_t woff[5];
    {
        size_t o = 0;
        for (int i = 0; i < 5; i++) {
            woff[i] = o;
            o += (size_t)Kps[i] * Ncs[i];
            int tot = Kps[i] * Ncs[i];
            w2bf<<<(tot + 255) / 256, 256>>>(W[i], wbf + woff[i], Ks[i], Kps[i], Ncs[i]);
        }
    }

    // 5 tensor-core layers
    const __nv_bfloat16* A = xbf;
    for (int i = 0; i < 5; i++) {
        int Nc = Ncs[i], Kp = Kps[i];
        int lda = (i == 0) ? KP0 : Ncs[i - 1];
        dim3 grid((Nc + 127) / 128, MM / 128);
        gemm_bf16<<<grid, 256>>>(A, wbf + woff[i], yf, lda, Kp, Nc);
        __nv_bfloat16* Hout = (i & 1) ? hb1 : hb0;
        int npb = 128 / (Nc >> 2) > 0 ? (128 / (Nc >> 2)) : 1;  // 512->1, 256->2, 64->8
        if (npb < 1) npb = 1;
        int bd_threads = npb * (Nc >> 2);
        agg_vec4<<<MM / npb, bd_threads>>>(yf, Hout, bias[i], Nc, (i & 1), npb);
        A = Hout;
    }

    // layer 5: K=64, Nc=3, then agg with bias + leaky -> feat fp32
    gemm_small_bf<<<MM / 256, 256>>>(A, W[5], yf);
    agg_last2<<<(MM * 3 + 255) / 256, 256>>>(yf, feat, bias[5]);

    // dense head
    dense_partial<<<dim3(DD / 128, KSPLIT), 128>>>(feat, Wd);
    dense_final<<<DD / 128, 128>>>(bd, out);
}